// round 1
// baseline (speedup 1.0000x reference)
#include <cuda_runtime.h>
#include <cstdint>

#define NSEQ 512
#define DMODEL 512
#define DH 64
#define NH 8
#define KTOP 51
#define ROWS 32
#define SCALE 2.8284271247461903f   // dh^0.25 = 64^0.25

// scratch (allocation-free rule: __device__ globals)
__device__ float g_Q[NSEQ * DMODEL];
__device__ float g_K[NSEQ * DMODEL];
__device__ float g_V[NSEQ * DMODEL];
__device__ float g_ctx[NSEQ * DMODEL];

// ---------------------------------------------------------------------------
// Generic 512x512x512 fp32 GEMM: C = A * B^T  (A,B row-major [512,512])
// Block tile 64x64, BK=16, 256 threads, 4x4 microtile.
// ---------------------------------------------------------------------------
__device__ __forceinline__ void gemm_abt_body(const float* __restrict__ A,
                                              const float* __restrict__ B,
                                              float* __restrict__ C)
{
    __shared__ float As[16][65];
    __shared__ float Bs[16][65];
    const int t  = threadIdx.x;
    const int tx = t & 15;        // micro row group
    const int ty = t >> 4;        // micro col group
    const int m0 = blockIdx.y * 64;
    const int n0 = blockIdx.x * 64;
    const int lr = t >> 4;        // load row base
    const int lc = t & 15;        // load col (k)
    float acc[4][4] = {};

    for (int k0 = 0; k0 < 512; k0 += 16) {
#pragma unroll
        for (int i = 0; i < 4; i++) {
            int r = lr + 16 * i;
            As[lc][r] = A[(m0 + r) * 512 + k0 + lc];
            Bs[lc][r] = B[(n0 + r) * 512 + k0 + lc];
        }
        __syncthreads();
#pragma unroll
        for (int kk = 0; kk < 16; kk++) {
            float a[4], b[4];
#pragma unroll
            for (int i = 0; i < 4; i++) a[i] = As[kk][tx + 16 * i];
#pragma unroll
            for (int j = 0; j < 4; j++) b[j] = Bs[kk][ty + 16 * j];
#pragma unroll
            for (int i = 0; i < 4; i++)
#pragma unroll
                for (int j = 0; j < 4; j++)
                    acc[i][j] = fmaf(a[i], b[j], acc[i][j]);
        }
        __syncthreads();
    }
#pragma unroll
    for (int i = 0; i < 4; i++)
#pragma unroll
        for (int j = 0; j < 4; j++)
            C[(m0 + tx + 16 * i) * 512 + n0 + ty + 16 * j] = acc[i][j];
}

// QKV fused: grid (8,8,3); z selects weight and destination
__global__ void qkv_kernel(const float* __restrict__ X,
                           const float* __restrict__ Wq,
                           const float* __restrict__ Wk,
                           const float* __restrict__ Wv)
{
    const float* B = (blockIdx.z == 0) ? Wq : (blockIdx.z == 1) ? Wk : Wv;
    float* C       = (blockIdx.z == 0) ? g_Q : (blockIdx.z == 1) ? g_K : g_V;
    gemm_abt_body(X, B, C);
}

// Output projection: out = ctx @ Wo^T
__global__ void out_kernel(const float* __restrict__ Wo, float* __restrict__ out)
{
    gemm_abt_body(g_ctx, Wo, out);
}

// ---------------------------------------------------------------------------
// Fused attention: per block = (32 query rows, 1 head).
//   scores -> |.|*scale in smem  ->  per-row top-51 threshold (warp binary
//   search on float bits)        ->  masked, normalized weighted sum of V.
// smem: Sc[32][513], Qs[32][65], KV[64][65], rowInv[32], budget[32]
// ---------------------------------------------------------------------------
#define SC_STRIDE 513
#define ATTN_SMEM_FLOATS (ROWS * SC_STRIDE + ROWS * 65 + 64 * 65 + ROWS)
#define ATTN_SMEM_BYTES  (ATTN_SMEM_FLOATS * 4 + ROWS * 4)

__global__ void attn_kernel()
{
    extern __shared__ float sm[];
    float* Sc     = sm;                         // ROWS * 513
    float* Qs     = Sc + ROWS * SC_STRIDE;      // ROWS * 65
    float* KV     = Qs + ROWS * 65;             // 64 * 65
    float* rowInv = KV + 64 * 65;               // ROWS
    int*   budget = (int*)(rowInv + ROWS);      // ROWS

    const int h    = blockIdx.y;
    const int row0 = blockIdx.x * ROWS;
    const int t    = threadIdx.x;

    // ---- load Q tile (ROWS x 64) ----
    for (int i = t; i < ROWS * DH; i += 256) {
        int r = i / DH, d = i % DH;
        Qs[r * 65 + d] = g_Q[(row0 + r) * DMODEL + h * DH + d];
    }

    // ---- phase 1: scores  Sc[r][j] = |q_r . k_j| * SCALE ----
    const int rr = t & 7;    // row group: rows 4*rr+i
    const int cc = t >> 3;   // col group: cols cc + 32*c
    for (int kt = 0; kt < 8; kt++) {
        __syncthreads();     // Qs ready (first iter) / prev compute done
        for (int i = t; i < 64 * DH; i += 256) {
            int r = i / DH, d = i % DH;
            KV[r * 65 + d] = g_K[(kt * 64 + r) * DMODEL + h * DH + d];
        }
        __syncthreads();
        float acc[4][2] = {};
#pragma unroll 8
        for (int d = 0; d < DH; d++) {
            float q[4], kv[2];
#pragma unroll
            for (int i = 0; i < 4; i++) q[i] = Qs[(rr * 4 + i) * 65 + d];
#pragma unroll
            for (int c = 0; c < 2; c++) kv[c] = KV[(cc + 32 * c) * 65 + d];
#pragma unroll
            for (int i = 0; i < 4; i++)
#pragma unroll
                for (int c = 0; c < 2; c++)
                    acc[i][c] = fmaf(q[i], kv[c], acc[i][c]);
        }
#pragma unroll
        for (int i = 0; i < 4; i++)
#pragma unroll
            for (int c = 0; c < 2; c++)
                Sc[(rr * 4 + i) * SC_STRIDE + kt * 64 + cc + 32 * c] =
                    fabsf(acc[i][c]) * SCALE;
    }
    __syncthreads();

    // ---- phase 2: per-row top-51 threshold + weight masking ----
    {
        const int warp = t >> 5, lane = t & 31;
        for (int r = warp; r < ROWS; r += 8) {
            float* row = Sc + r * SC_STRIDE;
            float v[16];
            unsigned u[16];
            float ssum = 0.f;
#pragma unroll
            for (int i = 0; i < 16; i++) {
                v[i] = row[lane + 32 * i];
                u[i] = __float_as_uint(v[i]);
                ssum += v[i];
            }
            // binary search for the bit pattern of the 51st largest value
            unsigned lo = 0u, hi = 0x7F800000u;
            while (lo < hi) {
                unsigned mid = lo + ((hi - lo + 1u) >> 1);
                int cnt = 0;
#pragma unroll
                for (int i = 0; i < 16; i++) cnt += (u[i] >= mid);
                cnt = __reduce_add_sync(0xffffffffu, cnt);
                if (cnt >= KTOP) lo = mid; else hi = mid - 1u;
            }
            const unsigned T = lo;
            int   cgt  = 0;
            float tsum = 0.f;
#pragma unroll
            for (int i = 0; i < 16; i++) {
                if (u[i] > T) { cgt++; tsum += v[i]; }
            }
            cgt = __reduce_add_sync(0xffffffffu, cgt);
#pragma unroll
            for (int o = 16; o; o >>= 1) {
                tsum += __shfl_xor_sync(0xffffffffu, tsum, o);
                ssum += __shfl_xor_sync(0xffffffffu, ssum, o);
            }
            const float Tf = __uint_as_float(T);
            tsum += (float)(KTOP - cgt) * Tf;
            if (lane == 0) {
                rowInv[r] = 1.0f / (tsum + 1e-8f * (ssum + 1e-8f));
                budget[r] = KTOP - cgt;   // slots left for values == T
            }
            __syncwarp();
#pragma unroll
            for (int i = 0; i < 16; i++) {
                float w;
                if (u[i] > T) {
                    w = v[i];
                } else if (u[i] == T) {
                    int p = atomicAdd(&budget[r], -1);
                    w = (p > 0) ? v[i] : 0.f;
                } else {
                    w = 0.f;
                }
                row[lane + 32 * i] = w;
            }
        }
    }
    __syncthreads();

    // ---- phase 3: out = (masked weights) @ V, scaled by rowInv ----
    float oacc[4][2] = {};
    for (int vt = 0; vt < 8; vt++) {
        for (int i = t; i < 64 * DH; i += 256) {
            int r = i / DH, d = i % DH;
            KV[r * 65 + d] = g_V[(vt * 64 + r) * DMODEL + h * DH + d];
        }
        __syncthreads();
#pragma unroll 8
        for (int kk = 0; kk < 64; kk++) {
            float w[4], vv[2];
#pragma unroll
            for (int i = 0; i < 4; i++)
                w[i] = Sc[(rr * 4 + i) * SC_STRIDE + vt * 64 + kk];
#pragma unroll
            for (int c = 0; c < 2; c++)
                vv[c] = KV[kk * 65 + cc + 32 * c];
#pragma unroll
            for (int i = 0; i < 4; i++)
#pragma unroll
                for (int c = 0; c < 2; c++)
                    oacc[i][c] = fmaf(w[i], vv[c], oacc[i][c]);
        }
        __syncthreads();
    }
#pragma unroll
    for (int i = 0; i < 4; i++)
#pragma unroll
        for (int c = 0; c < 2; c++)
            g_ctx[(row0 + rr * 4 + i) * DMODEL + h * DH + cc + 32 * c] =
                oacc[i][c] * rowInv[rr * 4 + i];
}

// ---------------------------------------------------------------------------
extern "C" void kernel_launch(void* const* d_in, const int* in_sizes, int n_in,
                              void* d_out, int out_size)
{
    const float* x  = (const float*)d_in[0];
    const float* Wq = (const float*)d_in[1];
    const float* Wk = (const float*)d_in[2];
    const float* Wv = (const float*)d_in[3];
    const float* Wo = (const float*)d_in[4];
    float* out = (float*)d_out;

    cudaFuncSetAttribute(attn_kernel,
                         cudaFuncAttributeMaxDynamicSharedMemorySize,
                         ATTN_SMEM_BYTES);

    qkv_kernel<<<dim3(8, 8, 3), 256>>>(x, Wq, Wk, Wv);
    attn_kernel<<<dim3(16, 8), 256, ATTN_SMEM_BYTES>>>();
    out_kernel<<<dim3(8, 8), 256>>>(Wo, out);
}

// round 2
// speedup vs baseline: 1.2721x; 1.2721x over previous
#include <cuda_runtime.h>
#include <cstdint>

#define NSEQ 512
#define DMODEL 512
#define DH 64
#define NH 8
#define KTOP 51
#define ROWS 32
#define SCALE 2.8284271247461903f   // dh^0.25

// scratch (allocation-free rule: __device__ globals)
__device__ float g_Q[NSEQ * DMODEL];
__device__ float g_K[NSEQ * DMODEL];
__device__ float g_V[NSEQ * DMODEL];
__device__ float g_ctx[NSEQ * DMODEL];

// ---------------------------------------------------------------------------
// 512x512x512 fp32 GEMM: C = A * B^T (row-major). Block tile 64x64, BK=32,
// 256 threads, 4x4 microtile, k-major smem (pad 68) -> float4 LDS both sides.
// ---------------------------------------------------------------------------
__device__ __forceinline__ void gemm_abt_body(const float* __restrict__ A,
                                              const float* __restrict__ B,
                                              float* __restrict__ C)
{
    __shared__ float As[32 * 68];
    __shared__ float Bs[32 * 68];
    const int t  = threadIdx.x;
    const int tx = t & 15;          // row group -> rows 4*tx..+3
    const int ty = t >> 4;          // col group -> cols 4*ty..+3
    const int m0 = blockIdx.y * 64;
    const int n0 = blockIdx.x * 64;
    float acc[4][4] = {};

    for (int k0 = 0; k0 < 512; k0 += 32) {
        __syncthreads();
#pragma unroll
        for (int f = t; f < 512; f += 256) {
            const int r  = f >> 3;
            const int kq = (f & 7) << 2;
            float4 a = *(const float4*)&A[(m0 + r) * 512 + k0 + kq];
            As[(kq + 0) * 68 + r] = a.x;
            As[(kq + 1) * 68 + r] = a.y;
            As[(kq + 2) * 68 + r] = a.z;
            As[(kq + 3) * 68 + r] = a.w;
            float4 b = *(const float4*)&B[(n0 + r) * 512 + k0 + kq];
            Bs[(kq + 0) * 68 + r] = b.x;
            Bs[(kq + 1) * 68 + r] = b.y;
            Bs[(kq + 2) * 68 + r] = b.z;
            Bs[(kq + 3) * 68 + r] = b.w;
        }
        __syncthreads();
#pragma unroll 8
        for (int kk = 0; kk < 32; kk++) {
            float4 a = *(const float4*)&As[kk * 68 + (tx << 2)];
            float4 b = *(const float4*)&Bs[kk * 68 + (ty << 2)];
            float av[4] = {a.x, a.y, a.z, a.w};
            float bv[4] = {b.x, b.y, b.z, b.w};
#pragma unroll
            for (int i = 0; i < 4; i++)
#pragma unroll
                for (int j = 0; j < 4; j++)
                    acc[i][j] = fmaf(av[i], bv[j], acc[i][j]);
        }
    }
#pragma unroll
    for (int i = 0; i < 4; i++) {
        float4 o = {acc[i][0], acc[i][1], acc[i][2], acc[i][3]};
        *(float4*)&C[(m0 + (tx << 2) + i) * 512 + n0 + (ty << 2)] = o;
    }
}

__global__ void qkv_kernel(const float* __restrict__ X,
                           const float* __restrict__ Wq,
                           const float* __restrict__ Wk,
                           const float* __restrict__ Wv)
{
    const float* B = (blockIdx.z == 0) ? Wq : (blockIdx.z == 1) ? Wk : Wv;
    float* C       = (blockIdx.z == 0) ? g_Q : (blockIdx.z == 1) ? g_K : g_V;
    gemm_abt_body(X, B, C);
}

__global__ void out_kernel(const float* __restrict__ Wo, float* __restrict__ out)
{
    gemm_abt_body(g_ctx, Wo, out);
}

// ---------------------------------------------------------------------------
// Fused attention, one block = (32 query rows, 1 head), 256 threads.
// smem (floats):
//   ScT [512][36]  scores transposed: ScT[j*36 + r]         (18432)
//   QT  [64][36]   Q transposed:      QT[d*36 + r]          ( 2304)
//   KV  buffer:    KT[d*132 + col] (64x132) | Vs[j*68 + c]  ( 8448)
//   rowInv[32], budget[32]
// ---------------------------------------------------------------------------
#define SCT_OFF   0
#define QT_OFF    (512 * 36)
#define KV_OFF    (QT_OFF + 64 * 36)
#define RI_OFF    (KV_OFF + 64 * 132)
#define BG_OFF    (RI_OFF + 32)
#define ATTN_SMEM_BYTES ((BG_OFF + 32) * 4)

__global__ void attn_kernel()
{
    extern __shared__ float sm[];
    float* ScT    = sm + SCT_OFF;
    float* QT     = sm + QT_OFF;
    float* KV     = sm + KV_OFF;
    float* rowInv = sm + RI_OFF;
    int*   budget = (int*)(sm + BG_OFF);

    const int h    = blockIdx.y;
    const int row0 = blockIdx.x * ROWS;
    const int t    = threadIdx.x;
    const int rr   = t & 7;    // row group: rows 4*rr..+3
    const int ct   = t >> 3;   // col group (phase1): cols 4*ct..+3 of 128

    // ---- load Q tile (32 x 64) transposed into QT[d][r] ----
    for (int f = t; f < ROWS * 16; f += 256) {
        const int r  = f >> 4;
        const int dq = (f & 15) << 2;
        float4 q = *(const float4*)&g_Q[(row0 + r) * DMODEL + h * DH + dq];
        QT[(dq + 0) * 36 + r] = q.x;
        QT[(dq + 1) * 36 + r] = q.y;
        QT[(dq + 2) * 36 + r] = q.z;
        QT[(dq + 3) * 36 + r] = q.w;
    }

    // ---- phase 1: ScT[j][r] = |q_r . k_j| * SCALE, 128 cols per pass ----
    for (int kt2 = 0; kt2 < 4; kt2++) {
        __syncthreads();
        for (int f = t; f < 128 * 16; f += 256) {
            const int col = f >> 4;
            const int dq  = (f & 15) << 2;
            float4 k = *(const float4*)&g_K[(kt2 * 128 + col) * DMODEL + h * DH + dq];
            KV[(dq + 0) * 132 + col] = k.x;
            KV[(dq + 1) * 132 + col] = k.y;
            KV[(dq + 2) * 132 + col] = k.z;
            KV[(dq + 3) * 132 + col] = k.w;
        }
        __syncthreads();
        float acc[4][4] = {};
#pragma unroll 8
        for (int d = 0; d < DH; d++) {
            float4 q = *(const float4*)&QT[d * 36 + (rr << 2)];
            float4 k = *(const float4*)&KV[d * 132 + (ct << 2)];
            float qv[4] = {q.x, q.y, q.z, q.w};
            float kv[4] = {k.x, k.y, k.z, k.w};
#pragma unroll
            for (int i = 0; i < 4; i++)
#pragma unroll
                for (int c = 0; c < 4; c++)
                    acc[i][c] = fmaf(qv[i], kv[c], acc[i][c]);
        }
#pragma unroll
        for (int c = 0; c < 4; c++) {
            float4 o = {fabsf(acc[0][c]) * SCALE, fabsf(acc[1][c]) * SCALE,
                        fabsf(acc[2][c]) * SCALE, fabsf(acc[3][c]) * SCALE};
            *(float4*)&ScT[(kt2 * 128 + (ct << 2) + c) * 36 + (rr << 2)] = o;
        }
    }
    __syncthreads();

    // ---- phase 2: per-row top-51 threshold + weight masking ----
    {
        const int warp = t >> 5, lane = t & 31;
        for (int r = warp; r < ROWS; r += 8) {
            float v[16];
            unsigned u[16];
            float ssum = 0.f;
#pragma unroll
            for (int i = 0; i < 16; i++) {
                v[i] = ScT[(lane + 32 * i) * 36 + r];
                u[i] = __float_as_uint(v[i]);
                ssum += v[i];
            }
            unsigned lo = 0u, hi = 0x7F800000u;
            while (lo < hi) {
                unsigned mid = lo + ((hi - lo + 1u) >> 1);
                int cnt = 0;
#pragma unroll
                for (int i = 0; i < 16; i++) cnt += (u[i] >= mid);
                cnt = __reduce_add_sync(0xffffffffu, cnt);
                if (cnt >= KTOP) lo = mid; else hi = mid - 1u;
            }
            const unsigned T = lo;
            int   cgt  = 0;
            float tsum = 0.f;
#pragma unroll
            for (int i = 0; i < 16; i++)
                if (u[i] > T) { cgt++; tsum += v[i]; }
            cgt = __reduce_add_sync(0xffffffffu, cgt);
#pragma unroll
            for (int o = 16; o; o >>= 1) {
                tsum += __shfl_xor_sync(0xffffffffu, tsum, o);
                ssum += __shfl_xor_sync(0xffffffffu, ssum, o);
            }
            const float Tf = __uint_as_float(T);
            tsum += (float)(KTOP - cgt) * Tf;
            if (lane == 0) {
                rowInv[r] = 1.0f / (tsum + 1e-8f * (ssum + 1e-8f));
                budget[r] = KTOP - cgt;   // slots for values == T
            }
            __syncwarp();
#pragma unroll
            for (int i = 0; i < 16; i++) {
                float w;
                if (u[i] > T) {
                    w = v[i];
                } else if (u[i] == T) {
                    int p = atomicAdd(&budget[r], -1);
                    w = (p > 0) ? v[i] : 0.f;
                } else {
                    w = 0.f;
                }
                ScT[(lane + 32 * i) * 36 + r] = w;
            }
        }
    }

    // ---- phase 3: out = W @ V, scaled by rowInv ----
    const int cc = t >> 3;           // col group: cols 2*cc..+1 of 64
    float oacc[4][2] = {};
    for (int vt = 0; vt < 8; vt++) {
        __syncthreads();             // also covers phase-2 completion on vt=0
        for (int f = t; f < 64 * 16; f += 256) {
            const int j  = f >> 4;
            const int cq = (f & 15) << 2;
            *(float4*)&KV[j * 68 + cq] =
                *(const float4*)&g_V[(vt * 64 + j) * DMODEL + h * DH + cq];
        }
        __syncthreads();
#pragma unroll 8
        for (int jj = 0; jj < 64; jj++) {
            const int j = vt * 64 + jj;
            float4 w = *(const float4*)&ScT[j * 36 + (rr << 2)];
            float2 v = *(const float2*)&KV[jj * 68 + (cc << 1)];
            float wv[4] = {w.x, w.y, w.z, w.w};
            oacc[0][0] = fmaf(wv[0], v.x, oacc[0][0]);
            oacc[0][1] = fmaf(wv[0], v.y, oacc[0][1]);
            oacc[1][0] = fmaf(wv[1], v.x, oacc[1][0]);
            oacc[1][1] = fmaf(wv[1], v.y, oacc[1][1]);
            oacc[2][0] = fmaf(wv[2], v.x, oacc[2][0]);
            oacc[2][1] = fmaf(wv[2], v.y, oacc[2][1]);
            oacc[3][0] = fmaf(wv[3], v.x, oacc[3][0]);
            oacc[3][1] = fmaf(wv[3], v.y, oacc[3][1]);
        }
    }
#pragma unroll
    for (int i = 0; i < 4; i++) {
        const float inv = rowInv[(rr << 2) + i];
        float2 o = {oacc[i][0] * inv, oacc[i][1] * inv};
        *(float2*)&g_ctx[(row0 + (rr << 2) + i) * DMODEL + h * DH + (cc << 1)] = o;
    }
}

// ---------------------------------------------------------------------------
extern "C" void kernel_launch(void* const* d_in, const int* in_sizes, int n_in,
                              void* d_out, int out_size)
{
    const float* x  = (const float*)d_in[0];
    const float* Wq = (const float*)d_in[1];
    const float* Wk = (const float*)d_in[2];
    const float* Wv = (const float*)d_in[3];
    const float* Wo = (const float*)d_in[4];
    float* out = (float*)d_out;

    cudaFuncSetAttribute(attn_kernel,
                         cudaFuncAttributeMaxDynamicSharedMemorySize,
                         ATTN_SMEM_BYTES);

    qkv_kernel<<<dim3(8, 8, 3), 256>>>(x, Wq, Wk, Wv);
    attn_kernel<<<dim3(16, 8), 256, ATTN_SMEM_BYTES>>>();
    out_kernel<<<dim3(8, 8), 256>>>(Wo, out);
}

// round 3
// speedup vs baseline: 1.6106x; 1.2661x over previous
#include <cuda_runtime.h>
#include <cstdint>

#define NSEQ 512
#define DMODEL 512
#define DH 64
#define NH 8
#define KTOP 51
#define ROWS 32
#define SCALE 2.8284271247461903f   // dh^0.25

// scratch (allocation-free rule: __device__ globals)
__device__ float g_Q[NSEQ * DMODEL];
__device__ float g_K[NSEQ * DMODEL];
__device__ float g_V[NSEQ * DMODEL];
__device__ float g_ctx[NSEQ * DMODEL];

// ---------------------------------------------------------------------------
// 512-K fp32 GEMM: C = A * B^T (row-major). Block tile 64x32, BK=32,
// 128 threads, 4x4 microtile, k-major smem, double-buffered + reg prefetch.
// ---------------------------------------------------------------------------
__device__ __forceinline__ void gemm64x32(const float* __restrict__ A,
                                          const float* __restrict__ B,
                                          float* __restrict__ C)
{
    __shared__ float As[2][32 * 68];
    __shared__ float Bs[2][32 * 36];
    const int t  = threadIdx.x;
    const int tx = t & 15;          // rows 4*tx..+3
    const int ty = t >> 4;          // cols 4*ty..+3 (0..7)
    const int m0 = blockIdx.y * 64;
    const int n0 = blockIdx.x * 32;

    // loader geometry
    const int ra  = t >> 3;          // A row   (0..63 over f=t,t+128,..)
    const int kqa = (t & 7) << 2;    // k quad
    float4 pa[4], pb[2];

    // prologue: load k0=0 tile
#pragma unroll
    for (int i = 0; i < 4; i++)
        pa[i] = *(const float4*)&A[(m0 + ra + (i << 4) * 1 + 16 * i * 0) * 512 + kqa]; // placeholder
    // (rewritten cleanly below)
#pragma unroll
    for (int i = 0; i < 4; i++) {
        const int f = t + (i << 7);
        pa[i] = *(const float4*)&A[(m0 + (f >> 3)) * 512 + ((f & 7) << 2)];
    }
#pragma unroll
    for (int i = 0; i < 2; i++) {
        const int f = t + (i << 7);
        pb[i] = *(const float4*)&B[(n0 + (f >> 3)) * 512 + ((f & 7) << 2)];
    }
#pragma unroll
    for (int i = 0; i < 4; i++) {
        const int f = t + (i << 7);
        const int r = f >> 3, kq = (f & 7) << 2;
        As[0][(kq + 0) * 68 + r] = pa[i].x;
        As[0][(kq + 1) * 68 + r] = pa[i].y;
        As[0][(kq + 2) * 68 + r] = pa[i].z;
        As[0][(kq + 3) * 68 + r] = pa[i].w;
    }
#pragma unroll
    for (int i = 0; i < 2; i++) {
        const int f = t + (i << 7);
        const int r = f >> 3, kq = (f & 7) << 2;
        Bs[0][(kq + 0) * 36 + r] = pb[i].x;
        Bs[0][(kq + 1) * 36 + r] = pb[i].y;
        Bs[0][(kq + 2) * 36 + r] = pb[i].z;
        Bs[0][(kq + 3) * 36 + r] = pb[i].w;
    }
    __syncthreads();

    float acc[4][4] = {};
    for (int kt = 0; kt < 16; kt++) {
        const int cur = kt & 1;
        if (kt < 15) {
            const int k0 = (kt + 1) << 5;
#pragma unroll
            for (int i = 0; i < 4; i++) {
                const int f = t + (i << 7);
                pa[i] = *(const float4*)&A[(m0 + (f >> 3)) * 512 + k0 + ((f & 7) << 2)];
            }
#pragma unroll
            for (int i = 0; i < 2; i++) {
                const int f = t + (i << 7);
                pb[i] = *(const float4*)&B[(n0 + (f >> 3)) * 512 + k0 + ((f & 7) << 2)];
            }
        }
#pragma unroll 8
        for (int kk = 0; kk < 32; kk++) {
            float4 a = *(const float4*)&As[cur][kk * 68 + (tx << 2)];
            float4 b = *(const float4*)&Bs[cur][kk * 36 + (ty << 2)];
            float av[4] = {a.x, a.y, a.z, a.w};
            float bv[4] = {b.x, b.y, b.z, b.w};
#pragma unroll
            for (int i = 0; i < 4; i++)
#pragma unroll
                for (int j = 0; j < 4; j++)
                    acc[i][j] = fmaf(av[i], bv[j], acc[i][j]);
        }
        if (kt < 15) {
            const int nxt = 1 - cur;
#pragma unroll
            for (int i = 0; i < 4; i++) {
                const int f = t + (i << 7);
                const int r = f >> 3, kq = (f & 7) << 2;
                As[nxt][(kq + 0) * 68 + r] = pa[i].x;
                As[nxt][(kq + 1) * 68 + r] = pa[i].y;
                As[nxt][(kq + 2) * 68 + r] = pa[i].z;
                As[nxt][(kq + 3) * 68 + r] = pa[i].w;
            }
#pragma unroll
            for (int i = 0; i < 2; i++) {
                const int f = t + (i << 7);
                const int r = f >> 3, kq = (f & 7) << 2;
                Bs[nxt][(kq + 0) * 36 + r] = pb[i].x;
                Bs[nxt][(kq + 1) * 36 + r] = pb[i].y;
                Bs[nxt][(kq + 2) * 36 + r] = pb[i].z;
                Bs[nxt][(kq + 3) * 36 + r] = pb[i].w;
            }
            __syncthreads();
        }
    }
#pragma unroll
    for (int i = 0; i < 4; i++) {
        float4 o = {acc[i][0], acc[i][1], acc[i][2], acc[i][3]};
        *(float4*)&C[(m0 + (tx << 2) + i) * 512 + n0 + (ty << 2)] = o;
    }
}

__global__ void __launch_bounds__(128) qkv_kernel(const float* __restrict__ X,
                                                  const float* __restrict__ Wq,
                                                  const float* __restrict__ Wk,
                                                  const float* __restrict__ Wv)
{
    const float* B = (blockIdx.z == 0) ? Wq : (blockIdx.z == 1) ? Wk : Wv;
    float* C       = (blockIdx.z == 0) ? g_Q : (blockIdx.z == 1) ? g_K : g_V;
    gemm64x32(X, B, C);
}

__global__ void __launch_bounds__(128) out_kernel(const float* __restrict__ Wo,
                                                  float* __restrict__ out)
{
    gemm64x32(g_ctx, Wo, out);
}

// ---------------------------------------------------------------------------
// Fused attention, one block = (32 query rows, 1 head), 256 threads.
// smem floats:
//   ScT [512*36]  scores transposed ScT[j*36+r]
//   QT  [64*36]   QT[d*36+r]
//   KT  [2][64*132]  phase-1 K ping-pong (reused as V ping-pong [2][64*68])
//   rowInv[32], budget[32]
// ---------------------------------------------------------------------------
#define SCT_OFF 0
#define QT_OFF  (512 * 36)
#define KT_OFF  (QT_OFF + 64 * 36)
#define KT_BUF  (64 * 132)
#define VB_BUF  (64 * 68)
#define RI_OFF  (KT_OFF + 2 * KT_BUF)
#define BG_OFF  (RI_OFF + 32)
#define ATTN_SMEM_BYTES ((BG_OFF + 32) * 4)

__global__ void __launch_bounds__(256, 1) attn_kernel()
{
    extern __shared__ float sm[];
    float* ScT    = sm + SCT_OFF;
    float* QT     = sm + QT_OFF;
    float* KT     = sm + KT_OFF;
    float* rowInv = sm + RI_OFF;
    int*   budget = (int*)(sm + BG_OFF);

    const int h    = blockIdx.y;
    const int row0 = blockIdx.x * ROWS;
    const int t    = threadIdx.x;
    const int rr   = t & 7;    // rows 4*rr..+3
    const int ct   = t >> 3;   // phase1 cols 4*ct..+3 (of 128)

    // ---- prologue: Q tile transposed + K chunk 0 ----
    {
        float4 pq[2];
#pragma unroll
        for (int i = 0; i < 2; i++) {
            const int f = t + (i << 8);
            pq[i] = *(const float4*)&g_Q[(row0 + (f >> 4)) * DMODEL + h * DH + ((f & 15) << 2)];
        }
        float4 pk[8];
#pragma unroll
        for (int i = 0; i < 8; i++) {
            const int f = t + (i << 8);
            pk[i] = *(const float4*)&g_K[(f >> 4) * DMODEL + h * DH + ((f & 15) << 2)];
        }
#pragma unroll
        for (int i = 0; i < 2; i++) {
            const int f = t + (i << 8);
            const int r = f >> 4, dq = (f & 15) << 2;
            QT[(dq + 0) * 36 + r] = pq[i].x;
            QT[(dq + 1) * 36 + r] = pq[i].y;
            QT[(dq + 2) * 36 + r] = pq[i].z;
            QT[(dq + 3) * 36 + r] = pq[i].w;
        }
#pragma unroll
        for (int i = 0; i < 8; i++) {
            const int f = t + (i << 8);
            const int col = f >> 4, dq = (f & 15) << 2;
            KT[(dq + 0) * 132 + col] = pk[i].x;
            KT[(dq + 1) * 132 + col] = pk[i].y;
            KT[(dq + 2) * 132 + col] = pk[i].z;
            KT[(dq + 3) * 132 + col] = pk[i].w;
        }
    }
    __syncthreads();

    // ---- phase 1: ScT[j][r] = |q_r . k_j| * SCALE, 128 cols/pass, ping-pong
    for (int kt2 = 0; kt2 < 4; kt2++) {
        const int cur = kt2 & 1;
        float4 pk[8];
        if (kt2 < 3) {
#pragma unroll
            for (int i = 0; i < 8; i++) {
                const int f = t + (i << 8);
                pk[i] = *(const float4*)&g_K[((kt2 + 1) * 128 + (f >> 4)) * DMODEL + h * DH + ((f & 15) << 2)];
            }
        }
        float acc[4][4] = {};
        const float* KTc = KT + cur * KT_BUF;
#pragma unroll 8
        for (int d = 0; d < DH; d++) {
            float4 q = *(const float4*)&QT[d * 36 + (rr << 2)];
            float4 k = *(const float4*)&KTc[d * 132 + (ct << 2)];
            float qv[4] = {q.x, q.y, q.z, q.w};
            float kv[4] = {k.x, k.y, k.z, k.w};
#pragma unroll
            for (int i = 0; i < 4; i++)
#pragma unroll
                for (int c = 0; c < 4; c++)
                    acc[i][c] = fmaf(qv[i], kv[c], acc[i][c]);
        }
#pragma unroll
        for (int c = 0; c < 4; c++) {
            float4 o = {fabsf(acc[0][c]) * SCALE, fabsf(acc[1][c]) * SCALE,
                        fabsf(acc[2][c]) * SCALE, fabsf(acc[3][c]) * SCALE};
            *(float4*)&ScT[(kt2 * 128 + (ct << 2) + c) * 36 + (rr << 2)] = o;
        }
        if (kt2 < 3) {
            float* KTn = KT + (1 - cur) * KT_BUF;
#pragma unroll
            for (int i = 0; i < 8; i++) {
                const int f = t + (i << 8);
                const int col = f >> 4, dq = (f & 15) << 2;
                KTn[(dq + 0) * 132 + col] = pk[i].x;
                KTn[(dq + 1) * 132 + col] = pk[i].y;
                KTn[(dq + 2) * 132 + col] = pk[i].z;
                KTn[(dq + 3) * 132 + col] = pk[i].w;
            }
            __syncthreads();
        }
    }
    __syncthreads();   // ScT complete

    // ---- issue V chunk-0 loads now; phase-2 compute hides their latency ----
    float4 pv[4];
#pragma unroll
    for (int i = 0; i < 4; i++) {
        const int f = t + (i << 8);
        pv[i] = *(const float4*)&g_V[(f >> 4) * DMODEL + h * DH + ((f & 15) << 2)];
    }

    // ---- phase 2: per-row top-51 threshold + weight masking ----
    {
        const int warp = t >> 5, lane = t & 31;
        for (int r = warp; r < ROWS; r += 8) {
            float v[16];
            unsigned u[16];
            float ssum = 0.f;
#pragma unroll
            for (int i = 0; i < 16; i++) {
                v[i] = ScT[(lane + 32 * i) * 36 + r];
                u[i] = __float_as_uint(v[i]);
                ssum += v[i];
            }
            unsigned lo = 0u, hi = 0x7F800000u;
            while (lo < hi) {
                unsigned mid = lo + ((hi - lo + 1u) >> 1);
                int cnt = 0;
#pragma unroll
                for (int i = 0; i < 16; i++) cnt += (u[i] >= mid);
                cnt = __reduce_add_sync(0xffffffffu, cnt);
                if (cnt >= KTOP) lo = mid; else hi = mid - 1u;
            }
            const unsigned T = lo;
            int   cgt  = 0;
            float tsum = 0.f;
#pragma unroll
            for (int i = 0; i < 16; i++)
                if (u[i] > T) { cgt++; tsum += v[i]; }
            cgt = __reduce_add_sync(0xffffffffu, cgt);
#pragma unroll
            for (int o = 16; o; o >>= 1) {
                tsum += __shfl_xor_sync(0xffffffffu, tsum, o);
                ssum += __shfl_xor_sync(0xffffffffu, ssum, o);
            }
            const float Tf = __uint_as_float(T);
            tsum += (float)(KTOP - cgt) * Tf;
            if (lane == 0) {
                rowInv[r] = 1.0f / (tsum + 1e-8f * (ssum + 1e-8f));
                budget[r] = KTOP - cgt;
            }
            __syncwarp();
#pragma unroll
            for (int i = 0; i < 16; i++) {
                float w;
                if (u[i] > T) {
                    w = v[i];
                } else if (u[i] == T) {
                    int p = atomicAdd(&budget[r], -1);
                    w = (p > 0) ? v[i] : 0.f;
                } else {
                    w = 0.f;
                }
                ScT[(lane + 32 * i) * 36 + r] = w;
            }
        }
    }
    // store V chunk 0 (row-major, pad 68) into buffer 0
    {
        float* Vb = KT;  // reuse KT region
#pragma unroll
        for (int i = 0; i < 4; i++) {
            const int f = t + (i << 8);
            *(float4*)&Vb[(f >> 4) * 68 + ((f & 15) << 2)] = pv[i];
        }
    }
    __syncthreads();   // covers phase-2 ScT writes + V buffer 0

    // ---- phase 3: out = W @ V (ping-pong V), scaled by rowInv ----
    const int cc = t >> 3;  // cols 2*cc..+1 (of 64)
    float oacc[4][2] = {};
    for (int vt = 0; vt < 8; vt++) {
        const int cur = vt & 1;
        if (vt < 7) {
#pragma unroll
            for (int i = 0; i < 4; i++) {
                const int f = t + (i << 8);
                pv[i] = *(const float4*)&g_V[((vt + 1) * 64 + (f >> 4)) * DMODEL + h * DH + ((f & 15) << 2)];
            }
        }
        const float* Vc = KT + cur * VB_BUF;
#pragma unroll 8
        for (int jj = 0; jj < 64; jj++) {
            const int j = vt * 64 + jj;
            float4 w = *(const float4*)&ScT[j * 36 + (rr << 2)];
            float2 v = *(const float2*)&Vc[jj * 68 + (cc << 1)];
            oacc[0][0] = fmaf(w.x, v.x, oacc[0][0]);
            oacc[0][1] = fmaf(w.x, v.y, oacc[0][1]);
            oacc[1][0] = fmaf(w.y, v.x, oacc[1][0]);
            oacc[1][1] = fmaf(w.y, v.y, oacc[1][1]);
            oacc[2][0] = fmaf(w.z, v.x, oacc[2][0]);
            oacc[2][1] = fmaf(w.z, v.y, oacc[2][1]);
            oacc[3][0] = fmaf(w.w, v.x, oacc[3][0]);
            oacc[3][1] = fmaf(w.w, v.y, oacc[3][1]);
        }
        if (vt < 7) {
            float* Vn = KT + (1 - cur) * VB_BUF;
#pragma unroll
            for (int i = 0; i < 4; i++) {
                const int f = t + (i << 8);
                *(float4*)&Vn[(f >> 4) * 68 + ((f & 15) << 2)] = pv[i];
            }
            __syncthreads();
        }
    }
#pragma unroll
    for (int i = 0; i < 4; i++) {
        const float inv = rowInv[(rr << 2) + i];
        float2 o = {oacc[i][0] * inv, oacc[i][1] * inv};
        *(float2*)&g_ctx[(row0 + (rr << 2) + i) * DMODEL + h * DH + (cc << 1)] = o;
    }
}

// ---------------------------------------------------------------------------
extern "C" void kernel_launch(void* const* d_in, const int* in_sizes, int n_in,
                              void* d_out, int out_size)
{
    const float* x  = (const float*)d_in[0];
    const float* Wq = (const float*)d_in[1];
    const float* Wk = (const float*)d_in[2];
    const float* Wv = (const float*)d_in[3];
    const float* Wo = (const float*)d_in[4];
    float* out = (float*)d_out;

    cudaFuncSetAttribute(attn_kernel,
                         cudaFuncAttributeMaxDynamicSharedMemorySize,
                         ATTN_SMEM_BYTES);

    qkv_kernel<<<dim3(16, 8, 3), 128>>>(x, Wq, Wk, Wv);
    attn_kernel<<<dim3(16, 8), 256, ATTN_SMEM_BYTES>>>();
    out_kernel<<<dim3(16, 8), 128>>>(Wo, out);
}

// round 4
// speedup vs baseline: 1.7895x; 1.1111x over previous
#include <cuda_runtime.h>
#include <cstdint>

#define NSEQ 512
#define DMODEL 512
#define DH 64
#define NH 8
#define KTOP 51
#define ROWS 32
#define SCALE 2.8284271247461903f   // dh^0.25

// scratch (allocation-free rule: __device__ globals)
__device__ float g_Q[NSEQ * DMODEL];
__device__ float g_K[NSEQ * DMODEL];
__device__ float g_V[NSEQ * DMODEL];
__device__ float g_ctx[NSEQ * DMODEL];
__device__ float g_qkvp[12 * NSEQ * DMODEL];  // qkv split-K partials (3 mats x 4 slices)
__device__ float g_outp[8 * NSEQ * DMODEL];   // out split-K partials (8 slices)

// ---------------------------------------------------------------------------
// cp.async helpers
// ---------------------------------------------------------------------------
__device__ __forceinline__ void cp16(uint32_t dst, const void* src) {
    asm volatile("cp.async.cg.shared.global [%0], [%1], 16;" :: "r"(dst), "l"(src));
}
__device__ __forceinline__ void cp_commit() { asm volatile("cp.async.commit_group;"); }
__device__ __forceinline__ void cp_wait1()  { asm volatile("cp.async.wait_group 1;"); }
__device__ __forceinline__ void cp_wait0()  { asm volatile("cp.async.wait_group 0;"); }

// ---------------------------------------------------------------------------
// GEMM partial: Cp(128x64 tile) = A[m, kbase:kbase+32*KITERS] * B^T
// 128 threads, micro 8x8, k-in-float4 smem layout, cp.async double buffer.
// smem (dynamic): As4 2*8*129 f4 | Bs4 2*8*65 f4 ; reused as Cs for output.
// ---------------------------------------------------------------------------
#define GEMM_SMEM_F4 (2 * 8 * 129 + 2 * 8 * 65)
#define GEMM_SMEM_BYTES (GEMM_SMEM_F4 * 16)

__device__ __forceinline__ void gemm128x64(const float* __restrict__ A,
                                           const float* __restrict__ B,
                                           float* __restrict__ Cp,
                                           int kbase, int kiters)
{
    extern __shared__ float4 gsm4[];
    float4* As4 = gsm4;                 // [buf][kq*129 + m]
    float4* Bs4 = gsm4 + 2 * 8 * 129;   // [buf][kq*65 + n]
    const int t  = threadIdx.x;
    const int mr = t & 15;              // rows mr + 16*i
    const int ng = t >> 4;              // cols ng + 8*j
    const int m0 = blockIdx.y * 128;
    const int n0 = blockIdx.x * 64;

    const uint32_t sA = (uint32_t)__cvta_generic_to_shared(As4);
    const uint32_t sB = (uint32_t)__cvta_generic_to_shared(Bs4);

    // issue loads for iteration kit into buffer buf
    auto issue = [&](int kit, int buf) {
        const int k0 = kbase + (kit << 5);
#pragma unroll
        for (int i = 0; i < 8; i++) {
            const int f = t + (i << 7);
            const int m = f >> 3, kq = f & 7;
            cp16(sA + (uint32_t)((buf * 1032 + kq * 129 + m) << 4),
                 &A[(m0 + m) * 512 + k0 + (kq << 2)]);
        }
#pragma unroll
        for (int i = 0; i < 4; i++) {
            const int f = t + (i << 7);
            const int n = f >> 3, kq = f & 7;
            cp16(sB + (uint32_t)((buf * 520 + kq * 65 + n) << 4),
                 &B[(n0 + n) * 512 + k0 + (kq << 2)]);
        }
        cp_commit();
    };

    float acc[8][8] = {};
    issue(0, 0);
    for (int kit = 0; kit < kiters; kit++) {
        const int buf = kit & 1;
        if (kit + 1 < kiters) { issue(kit + 1, buf ^ 1); cp_wait1(); }
        else                  { cp_wait0(); }
        __syncthreads();
        const float4* Ab = As4 + buf * 1032;
        const float4* Bb = Bs4 + buf * 520;
#pragma unroll
        for (int kq = 0; kq < 8; kq++) {
            float4 a4[8], b4[8];
#pragma unroll
            for (int i = 0; i < 8; i++) a4[i] = Ab[kq * 129 + mr + (i << 4)];
#pragma unroll
            for (int j = 0; j < 8; j++) b4[j] = Bb[kq * 65 + ng + (j << 3)];
#pragma unroll
            for (int i = 0; i < 8; i++)
#pragma unroll
                for (int j = 0; j < 8; j++) {
                    acc[i][j] = fmaf(a4[i].x, b4[j].x, acc[i][j]);
                    acc[i][j] = fmaf(a4[i].y, b4[j].y, acc[i][j]);
                    acc[i][j] = fmaf(a4[i].z, b4[j].z, acc[i][j]);
                    acc[i][j] = fmaf(a4[i].w, b4[j].w, acc[i][j]);
                }
        }
        __syncthreads();
    }

    // stage outputs through smem (stride 68 floats) for coalesced STG.128
    float* Cs = (float*)gsm4;
#pragma unroll
    for (int i = 0; i < 8; i++)
#pragma unroll
        for (int j = 0; j < 8; j++)
            Cs[(mr + (i << 4)) * 68 + ng + (j << 3)] = acc[i][j];
    __syncthreads();
#pragma unroll
    for (int i = 0; i < 16; i++) {
        const int f = t + (i << 7);
        const int m = f >> 4, q = f & 15;
        *(float4*)&Cp[(m0 + m) * 512 + n0 + (q << 2)] =
            *(const float4*)&Cs[m * 68 + (q << 2)];
    }
}

// qkv partials: grid (8, 4, 12); z = mat*4 + kslice (K=128 per slice)
__global__ void __launch_bounds__(128) qkv_part(const float* __restrict__ X,
                                                const float* __restrict__ Wq,
                                                const float* __restrict__ Wk,
                                                const float* __restrict__ Wv)
{
    const int z = blockIdx.z;
    const int mat = z >> 2, ks = z & 3;
    const float* B = (mat == 0) ? Wq : (mat == 1) ? Wk : Wv;
    gemm128x64(X, B, g_qkvp + z * (NSEQ * DMODEL), ks << 7, 4);
}

// out partials: grid (8, 4, 8); z = kslice (K=64 per slice)
__global__ void __launch_bounds__(128) out_part(const float* __restrict__ Wo)
{
    const int ks = blockIdx.z;
    gemm128x64(g_ctx, Wo, g_outp + ks * (NSEQ * DMODEL), ks << 6, 2);
}

// reduce 4 qkv partials -> g_Q/g_K/g_V.  grid 768 x 256 (f4 granularity)
__global__ void __launch_bounds__(256) reduce_qkv()
{
    const int idx = blockIdx.x * 256 + threadIdx.x;   // 0 .. 196607
    const int mat = idx >> 16, r = idx & 0xFFFF;
    const float4* p = (const float4*)g_qkvp;
    float4 a = p[(mat * 4 + 0) * 65536 + r];
    float4 b = p[(mat * 4 + 1) * 65536 + r];
    float4 c = p[(mat * 4 + 2) * 65536 + r];
    float4 d = p[(mat * 4 + 3) * 65536 + r];
    float4 s = {a.x + b.x + c.x + d.x, a.y + b.y + c.y + d.y,
                a.z + b.z + c.z + d.z, a.w + b.w + c.w + d.w};
    float4* o = (mat == 0) ? (float4*)g_Q : (mat == 1) ? (float4*)g_K : (float4*)g_V;
    o[r] = s;
}

// reduce 8 out partials -> d_out.  grid 256 x 256
__global__ void __launch_bounds__(256) reduce_out(float* __restrict__ out)
{
    const int r = blockIdx.x * 256 + threadIdx.x;     // 0 .. 65535
    const float4* p = (const float4*)g_outp;
    float4 s = {0.f, 0.f, 0.f, 0.f};
#pragma unroll
    for (int k = 0; k < 8; k++) {
        float4 v = p[k * 65536 + r];
        s.x += v.x; s.y += v.y; s.z += v.z; s.w += v.w;
    }
    ((float4*)out)[r] = s;
}

// ---------------------------------------------------------------------------
// Fused attention: block = (32 query rows, 1 head), 256 threads.
// smem floats:
//   ScT [512*36]       scores ScT[j*36 + r]  (later reused as Pbuf)
//   Q4  [16*33] f4     Q4[d4*33 + r]    (float4 over d)
//   KV  [34816]        phase1: K4[d4*513 + col] (f4 over d, 32832 floats)
//                      phase3: V4[j*17 + c4]    (straight f4, 34816 floats)
//   rowInv[32], budget[32]
// ---------------------------------------------------------------------------
#define SCT_OFF 0
#define Q4_OFF  18432
#define KV_OFF  (Q4_OFF + 16 * 33 * 4)
#define RI_OFF  (KV_OFF + 34816)
#define BG_OFF  (RI_OFF + 32)
#define ATTN_SMEM_BYTES ((BG_OFF + 32) * 4)

__global__ void __launch_bounds__(256, 1) attn_kernel()
{
    extern __shared__ float sm[];
    float*  ScT    = sm + SCT_OFF;
    float4* Q4     = (float4*)(sm + Q4_OFF);
    float4* KV4    = (float4*)(sm + KV_OFF);
    float*  rowInv = sm + RI_OFF;
    int*    budget = (int*)(sm + BG_OFF);

    const int h    = blockIdx.y;
    const int row0 = blockIdx.x * ROWS;
    const int t    = threadIdx.x;

    // ---- load Q (f4-over-d) and K (f4-over-d) ----
#pragma unroll
    for (int i = 0; i < 2; i++) {
        const int f = t + (i << 8);
        const int r = f >> 4, d4 = f & 15;
        Q4[d4 * 33 + r] = *(const float4*)&g_Q[(row0 + r) * DMODEL + h * DH + (d4 << 2)];
    }
#pragma unroll
    for (int i = 0; i < 32; i++) {
        const int f = t + (i << 8);
        const int col = f >> 4, d4 = f & 15;
        KV4[d4 * 513 + col] = *(const float4*)&g_K[col * DMODEL + h * DH + (d4 << 2)];
    }
    __syncthreads();

    // ---- phase 1: scores, micro 4 rows (rr+8i) x 16 cols (tc+32cc) ----
    {
        const int rr = t & 7;
        const int tc = t >> 3;
        float acc[4][16] = {};
        for (int d4 = 0; d4 < 16; d4++) {
            float4 q4[4];
#pragma unroll
            for (int i = 0; i < 4; i++) q4[i] = Q4[d4 * 33 + rr + (i << 3)];
#pragma unroll
            for (int cc = 0; cc < 16; cc++) {
                const float4 k4 = KV4[d4 * 513 + tc + (cc << 5)];
#pragma unroll
                for (int i = 0; i < 4; i++) {
                    float s = acc[i][cc];
                    s = fmaf(q4[i].x, k4.x, s);
                    s = fmaf(q4[i].y, k4.y, s);
                    s = fmaf(q4[i].z, k4.z, s);
                    s = fmaf(q4[i].w, k4.w, s);
                    acc[i][cc] = s;
                }
            }
        }
#pragma unroll
        for (int cc = 0; cc < 16; cc++)
#pragma unroll
            for (int i = 0; i < 4; i++)
                ScT[(tc + (cc << 5)) * 36 + rr + (i << 3)] = fabsf(acc[i][cc]) * SCALE;
    }
    __syncthreads();   // scores done, K region dead

    // ---- copy V into KV region (straight float4, V4[j*17 + c4]) ----
#pragma unroll
    for (int i = 0; i < 32; i++) {
        const int f = t + (i << 8);
        const int j = f >> 4, c4 = f & 15;
        KV4[j * 17 + c4] = *(const float4*)&g_V[j * DMODEL + h * DH + (c4 << 2)];
    }

    // ---- phase 2: per-row top-51 threshold + weight masking ----
    {
        const int warp = t >> 5, lane = t & 31;
        for (int r = warp; r < ROWS; r += 8) {
            float v[16];
            unsigned u[16];
            float ssum = 0.f;
#pragma unroll
            for (int i = 0; i < 16; i++) {
                v[i] = ScT[(lane + 32 * i) * 36 + r];
                u[i] = __float_as_uint(v[i]);
                ssum += v[i];
            }
            unsigned lo = 0u, hi = 0x7F800000u;
            while (lo < hi) {
                unsigned mid = lo + ((hi - lo + 1u) >> 1);
                int cnt = 0;
#pragma unroll
                for (int i = 0; i < 16; i++) cnt += (u[i] >= mid);
                cnt = __reduce_add_sync(0xffffffffu, cnt);
                if (cnt >= KTOP) lo = mid; else hi = mid - 1u;
            }
            const unsigned T = lo;
            int   cgt  = 0;
            float tsum = 0.f;
#pragma unroll
            for (int i = 0; i < 16; i++)
                if (u[i] > T) { cgt++; tsum += v[i]; }
            cgt = __reduce_add_sync(0xffffffffu, cgt);
#pragma unroll
            for (int o = 16; o; o >>= 1) {
                tsum += __shfl_xor_sync(0xffffffffu, tsum, o);
                ssum += __shfl_xor_sync(0xffffffffu, ssum, o);
            }
            const float Tf = __uint_as_float(T);
            tsum += (float)(KTOP - cgt) * Tf;
            if (lane == 0) {
                rowInv[r] = 1.0f / (tsum + 1e-8f * (ssum + 1e-8f));
                budget[r] = KTOP - cgt;
            }
            __syncwarp();
#pragma unroll
            for (int i = 0; i < 16; i++) {
                float w;
                if (u[i] > T) {
                    w = v[i];
                } else if (u[i] == T) {
                    int p = atomicAdd(&budget[r], -1);
                    w = (p > 0) ? v[i] : 0.f;
                } else {
                    w = 0.f;
                }
                ScT[(lane + 32 * i) * 36 + r] = w;
            }
        }
    }
    __syncthreads();   // masked weights + V tile ready

    // ---- phase 3: out = W @ V; 4 j-segments x (8 rowgrp x 8 colgrp) ----
    {
        const int s  = t >> 6;        // j segment
        const int u  = t & 63;
        const int rg = u & 7;         // rows 4*rg .. +3
        const int cg = u >> 3;        // col quads cg, cg+8
        float acc[4][2][4] = {};
        const int jbase = s << 7;
#pragma unroll 4
        for (int jj = 0; jj < 128; jj++) {
            const int j = jbase + jj;
            const float4 w  = *(const float4*)&ScT[j * 36 + (rg << 2)];
            const float4 v0 = KV4[j * 17 + cg];
            const float4 v1 = KV4[j * 17 + cg + 8];
            const float wv[4] = {w.x, w.y, w.z, w.w};
#pragma unroll
            for (int i = 0; i < 4; i++) {
                acc[i][0][0] = fmaf(wv[i], v0.x, acc[i][0][0]);
                acc[i][0][1] = fmaf(wv[i], v0.y, acc[i][0][1]);
                acc[i][0][2] = fmaf(wv[i], v0.z, acc[i][0][2]);
                acc[i][0][3] = fmaf(wv[i], v0.w, acc[i][0][3]);
                acc[i][1][0] = fmaf(wv[i], v1.x, acc[i][1][0]);
                acc[i][1][1] = fmaf(wv[i], v1.y, acc[i][1][1]);
                acc[i][1][2] = fmaf(wv[i], v1.z, acc[i][1][2]);
                acc[i][1][3] = fmaf(wv[i], v1.w, acc[i][1][3]);
            }
        }
        __syncthreads();   // all ScT reads done -> reuse as partial buffer
        float* P = ScT;
        if (s > 0) {
#pragma unroll
            for (int i = 0; i < 4; i++)
#pragma unroll
                for (int o = 0; o < 2; o++)
                    *(float4*)&P[((s - 1) << 11) + ((rg << 2) + i) * 64 + ((cg + (o << 3)) << 2)] =
                        *(const float4*)acc[i][o];
        }
        __syncthreads();
        if (s == 0) {
#pragma unroll
            for (int i = 0; i < 4; i++) {
                const int r = (rg << 2) + i;
                const float inv = rowInv[r];
#pragma unroll
                for (int o = 0; o < 2; o++) {
                    const int coff = ((cg + (o << 3)) << 2);
                    float4 v = *(const float4*)acc[i][o];
#pragma unroll
                    for (int sgi = 0; sgi < 3; sgi++) {
                        const float4 pv = *(const float4*)&P[(sgi << 11) + r * 64 + coff];
                        v.x += pv.x; v.y += pv.y; v.z += pv.z; v.w += pv.w;
                    }
                    v.x *= inv; v.y *= inv; v.z *= inv; v.w *= inv;
                    *(float4*)&g_ctx[(row0 + r) * DMODEL + h * DH + coff] = v;
                }
            }
        }
    }
}

// ---------------------------------------------------------------------------
extern "C" void kernel_launch(void* const* d_in, const int* in_sizes, int n_in,
                              void* d_out, int out_size)
{
    const float* x  = (const float*)d_in[0];
    const float* Wq = (const float*)d_in[1];
    const float* Wk = (const float*)d_in[2];
    const float* Wv = (const float*)d_in[3];
    const float* Wo = (const float*)d_in[4];
    float* out = (float*)d_out;

    cudaFuncSetAttribute(qkv_part, cudaFuncAttributeMaxDynamicSharedMemorySize, GEMM_SMEM_BYTES);
    cudaFuncSetAttribute(out_part, cudaFuncAttributeMaxDynamicSharedMemorySize, GEMM_SMEM_BYTES);
    cudaFuncSetAttribute(attn_kernel, cudaFuncAttributeMaxDynamicSharedMemorySize, ATTN_SMEM_BYTES);

    qkv_part<<<dim3(8, 4, 12), 128, GEMM_SMEM_BYTES>>>(x, Wq, Wk, Wv);
    reduce_qkv<<<768, 256>>>();
    attn_kernel<<<dim3(16, 8), 256, ATTN_SMEM_BYTES>>>();
    out_part<<<dim3(8, 4, 8), 128, GEMM_SMEM_BYTES>>>(Wo);
    reduce_out<<<256, 256>>>(out);
}